// round 15
// baseline (speedup 1.0000x reference)
#include <cuda_runtime.h>

// x: (4096, 32, 500) f32, W: (1,32) f32, b: (1,) f32 -> out: (4096,) f32
// out[s] = mean_a | sum_c W[c]*x[s][c][a] + b | + 0.01
//
// FINAL: converged kernel. Pure HBM/LTS-bound stream at ~6.45 TB/s (chip
// ceiling for this pattern; verified invariant to MLP depth, occupancy,
// cache policy, CTA shape across R2-R13). One CTA per sample, 128 threads,
// float4 stream, W staged in smem, two-level warp reduction.

#define N_SAMPLES 4096
#define N_CH      32
#define N_ASSETS  500
#define VEC4_PER_ROW 125          // 500 / 4
#define THREADS   128

__global__ __launch_bounds__(THREADS)
void gamma_kernel(const float* __restrict__ x,
                  const float* __restrict__ W,
                  const float* __restrict__ b,
                  float* __restrict__ out)
{
    const int s   = blockIdx.x;
    const int tid = threadIdx.x;

    __shared__ float ws[N_CH];
    __shared__ float bs;
    if (tid < N_CH) ws[tid] = W[tid];
    if (tid == N_CH) bs = b[0];
    __syncthreads();

    const float* xs = x + (size_t)s * (N_CH * N_ASSETS);

    float4 acc = make_float4(0.f, 0.f, 0.f, 0.f);

    if (tid < VEC4_PER_ROW) {
        const float4* base = reinterpret_cast<const float4*>(xs) + tid;
        #pragma unroll
        for (int c = 0; c < N_CH; ++c) {
            const float wc = ws[c];
            float4 v = base[c * VEC4_PER_ROW];
            acc.x = fmaf(wc, v.x, acc.x);
            acc.y = fmaf(wc, v.y, acc.y);
            acc.z = fmaf(wc, v.z, acc.z);
            acc.w = fmaf(wc, v.w, acc.w);
        }
    }

    const float bv = bs;
    float part = 0.f;
    if (tid < VEC4_PER_ROW) {
        part = fabsf(acc.x + bv) + fabsf(acc.y + bv)
             + fabsf(acc.z + bv) + fabsf(acc.w + bv);
    }

    // warp reduce
    #pragma unroll
    for (int off = 16; off > 0; off >>= 1)
        part += __shfl_xor_sync(0xFFFFFFFFu, part, off);

    __shared__ float warp_sums[THREADS / 32];
    const int wid = tid >> 5;
    const int lid = tid & 31;
    if (lid == 0) warp_sums[wid] = part;
    __syncthreads();

    if (tid == 0) {
        float total = warp_sums[0] + warp_sums[1] + warp_sums[2] + warp_sums[3];
        out[s] = total * (1.0f / (float)N_ASSETS) + 0.01f;
    }
}

extern "C" void kernel_launch(void* const* d_in, const int* in_sizes, int n_in,
                              void* d_out, int out_size)
{
    const float* x = (const float*)d_in[0];
    const float* W = (const float*)d_in[1];
    const float* b = (const float*)d_in[2];
    float* out = (float*)d_out;
    (void)in_sizes; (void)n_in; (void)out_size;

    gamma_kernel<<<N_SAMPLES, THREADS>>>(x, W, b, out);
}

// round 16
// speedup vs baseline: 1.0030x; 1.0030x over previous
#include <cuda_runtime.h>

// x: (4096, 32, 500) f32, W: (1,32) f32, b: (1,) f32 -> out: (4096,) f32
// out[s] = mean_a | sum_c W[c]*x[s][c][a] + b | + 0.01
//
// FINAL (R1 shape): best recorded device time of the session (40.9us ncu).
// Pure HBM-bound read-once stream at the ~6.45 TB/s achievable ceiling
// (invariant to MLP depth, occupancy, cache policy, CTA shape — R2-R15).
// Minimal prologue: no smem staging, no barrier before the mainloop; first
// stream loads issue immediately at CTA start. W reads are L1-resident
// broadcasts (proven perf-neutral vs smem staging).

#define N_SAMPLES 4096
#define N_CH      32
#define N_ASSETS  500
#define VEC4_PER_ROW 125          // 500 / 4
#define THREADS   128

__global__ __launch_bounds__(THREADS)
void gamma_kernel(const float* __restrict__ x,
                  const float* __restrict__ W,
                  const float* __restrict__ b,
                  float* __restrict__ out)
{
    const int s   = blockIdx.x;
    const int tid = threadIdx.x;

    const float bv = __ldg(b);
    const float* xs = x + (size_t)s * (N_CH * N_ASSETS);

    float4 acc = make_float4(0.f, 0.f, 0.f, 0.f);

    if (tid < VEC4_PER_ROW) {
        const float* base = xs + tid * 4;
        #pragma unroll
        for (int c = 0; c < N_CH; ++c) {
            const float wc = __ldg(&W[c]);
            float4 v = *reinterpret_cast<const float4*>(base + c * N_ASSETS);
            acc.x = fmaf(wc, v.x, acc.x);
            acc.y = fmaf(wc, v.y, acc.y);
            acc.z = fmaf(wc, v.z, acc.z);
            acc.w = fmaf(wc, v.w, acc.w);
        }
    }

    float part = 0.f;
    if (tid < VEC4_PER_ROW) {
        part = fabsf(acc.x + bv) + fabsf(acc.y + bv)
             + fabsf(acc.z + bv) + fabsf(acc.w + bv);
    }

    // warp reduce
    #pragma unroll
    for (int off = 16; off > 0; off >>= 1)
        part += __shfl_xor_sync(0xFFFFFFFFu, part, off);

    __shared__ float warp_sums[THREADS / 32];
    const int wid = tid >> 5;
    const int lid = tid & 31;
    if (lid == 0) warp_sums[wid] = part;
    __syncthreads();

    if (tid == 0) {
        float total = warp_sums[0] + warp_sums[1] + warp_sums[2] + warp_sums[3];
        out[s] = total * (1.0f / (float)N_ASSETS) + 0.01f;
    }
}

extern "C" void kernel_launch(void* const* d_in, const int* in_sizes, int n_in,
                              void* d_out, int out_size)
{
    const float* x = (const float*)d_in[0];
    const float* W = (const float*)d_in[1];
    const float* b = (const float*)d_in[2];
    float* out = (float*)d_out;
    (void)in_sizes; (void)n_in; (void)out_size;

    gamma_kernel<<<N_SAMPLES, THREADS>>>(x, W, b, out);
}

// round 17
// speedup vs baseline: 1.0386x; 1.0355x over previous
#include <cuda_runtime.h>

// x: (4096, 32, 500) f32, W: (1,32) f32, b: (1,) f32 -> out: (4096,) f32
// out[s] = mean_a | sum_c W[c]*x[s][c][a] + b | + 0.01
//
// R1 skeleton + L2::256B fetch-granularity promotion on the dense read-once
// stream (inline PTX; ptxas never emits this from C++). Each 256B window is
// fully consumed by consecutive threads, so promotion is overfetch-free and
// halves DRAM request count per byte.

#define N_SAMPLES 4096
#define N_CH      32
#define N_ASSETS  500
#define VEC4_PER_ROW 125          // 500 / 4
#define THREADS   128

__device__ __forceinline__ float4 ldg_nc_256(const float4* p)
{
    float4 v;
    asm volatile("ld.global.nc.L2::256B.v4.f32 {%0,%1,%2,%3}, [%4];"
                 : "=f"(v.x), "=f"(v.y), "=f"(v.z), "=f"(v.w)
                 : "l"(p));
    return v;
}

__global__ __launch_bounds__(THREADS)
void gamma_kernel(const float* __restrict__ x,
                  const float* __restrict__ W,
                  const float* __restrict__ b,
                  float* __restrict__ out)
{
    const int s   = blockIdx.x;
    const int tid = threadIdx.x;

    const float bv = __ldg(b);
    const float* xs = x + (size_t)s * (N_CH * N_ASSETS);

    float4 acc = make_float4(0.f, 0.f, 0.f, 0.f);

    if (tid < VEC4_PER_ROW) {
        const float* base = xs + tid * 4;
        #pragma unroll
        for (int c = 0; c < N_CH; ++c) {
            const float wc = __ldg(&W[c]);
            float4 v = ldg_nc_256(reinterpret_cast<const float4*>(base + c * N_ASSETS));
            acc.x = fmaf(wc, v.x, acc.x);
            acc.y = fmaf(wc, v.y, acc.y);
            acc.z = fmaf(wc, v.z, acc.z);
            acc.w = fmaf(wc, v.w, acc.w);
        }
    }

    float part = 0.f;
    if (tid < VEC4_PER_ROW) {
        part = fabsf(acc.x + bv) + fabsf(acc.y + bv)
             + fabsf(acc.z + bv) + fabsf(acc.w + bv);
    }

    // warp reduce
    #pragma unroll
    for (int off = 16; off > 0; off >>= 1)
        part += __shfl_xor_sync(0xFFFFFFFFu, part, off);

    __shared__ float warp_sums[THREADS / 32];
    const int wid = tid >> 5;
    const int lid = tid & 31;
    if (lid == 0) warp_sums[wid] = part;
    __syncthreads();

    if (tid == 0) {
        float total = warp_sums[0] + warp_sums[1] + warp_sums[2] + warp_sums[3];
        out[s] = total * (1.0f / (float)N_ASSETS) + 0.01f;
    }
}

extern "C" void kernel_launch(void* const* d_in, const int* in_sizes, int n_in,
                              void* d_out, int out_size)
{
    const float* x = (const float*)d_in[0];
    const float* W = (const float*)d_in[1];
    const float* b = (const float*)d_in[2];
    float* out = (float*)d_out;
    (void)in_sizes; (void)n_in; (void)out_size;

    gamma_kernel<<<N_SAMPLES, THREADS>>>(x, W, b, out);
}